// round 1
// baseline (speedup 1.0000x reference)
#include <cuda_runtime.h>

// Shapes
#define NB     2
#define NH     16
#define SEQ    2048
#define DMODEL 1024
#define DHEAD  64
#define NROWS  (NB*SEQ)          // 4096
#define BHS    (NB*NH*SEQ)       // 65536 rows of 64

// Scratch: [b][h][s][d] layout, fp32
__device__ float g_q[NB*NH*SEQ*DHEAD];
__device__ float g_k[NB*NH*SEQ*DHEAD];
__device__ float g_v[NB*NH*SEQ*DHEAD];
__device__ float g_z[NB*NH*SEQ*DHEAD];

// ---------------------------------------------------------------------------
// Kernel 1: fused QKV projection.  C = x @ W^T + bias, scattered to
// [b][h][s][d].  NT GEMM, M=4096, N=3072 (Wq|Wk|Wv), K=1024.
// 64x64x16 tiles, 256 threads, 4x4 per thread.
// ---------------------------------------------------------------------------
__global__ void qkv_gemm(const float* __restrict__ x,
                         const float* __restrict__ Wq, const float* __restrict__ bq,
                         const float* __restrict__ Wk, const float* __restrict__ bk,
                         const float* __restrict__ Wv, const float* __restrict__ bv)
{
    __shared__ float As[16][65];
    __shared__ float Bs[16][65];

    int bx = blockIdx.x;              // 0..47 (n tiles)
    int by = blockIdx.y;              // 0..63 (m tiles)
    int which = bx >> 4;              // 0=q 1=k 2=v
    const float* W    = (which == 0) ? Wq : (which == 1) ? Wk : Wv;
    const float* bias = (which == 0) ? bq : (which == 1) ? bk : bv;
    float* outbuf     = (which == 0) ? g_q : (which == 1) ? g_k : g_v;
    int n0 = (bx & 15) * 64;          // within the 1024-wide weight
    int m0 = by * 64;

    int t   = threadIdx.x;
    int ty  = t >> 4, tx = t & 15;
    int lr  = t >> 4;                 // load row group (0..15)
    int lc  = t & 15;                 // load k col   (0..15)

    float acc[4][4] = {};

    for (int k0 = 0; k0 < DMODEL; k0 += 16) {
        #pragma unroll
        for (int r = 0; r < 4; r++) {
            int row = lr + r * 16;
            As[lc][row] = x[(m0 + row) * DMODEL + k0 + lc];
            Bs[lc][row] = W[(n0 + row) * DMODEL + k0 + lc];
        }
        __syncthreads();
        #pragma unroll
        for (int kk = 0; kk < 16; kk++) {
            float a[4], b[4];
            #pragma unroll
            for (int i = 0; i < 4; i++) a[i] = As[kk][ty * 4 + i];
            #pragma unroll
            for (int j = 0; j < 4; j++) b[j] = Bs[kk][tx * 4 + j];
            #pragma unroll
            for (int i = 0; i < 4; i++)
                #pragma unroll
                for (int j = 0; j < 4; j++)
                    acc[i][j] += a[i] * b[j];
        }
        __syncthreads();
    }

    int h = n0 >> 6;                  // tile is 64-aligned: single head
    #pragma unroll
    for (int i = 0; i < 4; i++) {
        int m = m0 + ty * 4 + i;
        int b = m >> 11, s = m & (SEQ - 1);
        float* orow = outbuf + (((b * NH + h) * SEQ) + s) * DHEAD;
        #pragma unroll
        for (int j = 0; j < 4; j++) {
            int n = n0 + tx * 4 + j;
            orow[n & 63] = acc[i][j] + bias[n];
        }
    }
}

// ---------------------------------------------------------------------------
// Kernel 2: RMSNorm + RoPE on q and k (in place).  One warp per (tensor,b,h,s)
// row of 64.  Lane handles the interleaved pair (2*lane, 2*lane+1).
// ---------------------------------------------------------------------------
__global__ void normrope(const float* __restrict__ nw)
{
    int gw   = (blockIdx.x * blockDim.x + threadIdx.x) >> 5;
    int lane = threadIdx.x & 31;
    int sel  = gw >> 16;              // 0=q 1=k  (65536 rows each)
    int idx  = gw & 65535;
    float* buf = sel ? g_k : g_q;
    int s = idx & (SEQ - 1);          // sequence position for RoPE

    float2* p = reinterpret_cast<float2*>(buf + (size_t)idx * DHEAD) + lane;
    float2 v = *p;

    float ss = v.x * v.x + v.y * v.y;
    #pragma unroll
    for (int off = 16; off > 0; off >>= 1)
        ss += __shfl_xor_sync(0xffffffffu, ss, off);
    float scale = rsqrtf(ss * (1.0f / 64.0f) + 1.1920929e-7f);

    int d0 = lane * 2, d1 = d0 + 1;
    float xn = v.x * scale * nw[d0];
    float yn = v.y * scale * nw[d1];

    // emb[d] = s * invfreq[d mod 32], invfreq[j] = 10000^(-j/32)
    int j0 = d0 & 31, j1 = d1 & 31;
    const float c = 9.210340371976184f / 32.0f;   // ln(10000)/32
    float ang0 = (float)s * expf(-(float)j0 * c);
    float ang1 = (float)s * expf(-(float)j1 * c);
    float c0 = cosf(ang0), s0 = sinf(ang0);
    float c1 = cosf(ang1), s1 = sinf(ang1);

    float2 o;
    o.x = xn * c0 - yn * s0;          // out[2i]   = x[2i]c - x[2i+1]s
    o.y = yn * c1 + xn * s1;          // out[2i+1] = x[2i+1]c + x[2i]s
    *p = o;
}

// ---------------------------------------------------------------------------
// Kernel 3: attention.  Per (b,h, q-tile of 64): stream causal k-tiles,
// S = (Q.K^T / 64)^2 masked, Z += S.V.  No softmax -> pure accumulation.
// ---------------------------------------------------------------------------
__global__ void attn_kernel()
{
    extern __shared__ float sm[];
    float* Qs = sm;                    // [64][65]
    float* Ks = Qs + 64 * 65;          // [64][65]
    float* Ss = Ks + 64 * 65;          // [64][68]
    float* Vs = Ss + 64 * 68;          // [64][64]

    int qt = blockIdx.x, h = blockIdx.y, b = blockIdx.z;
    int q0 = qt * 64;
    const float* qbase = g_q + ((b * NH + h) * SEQ) * DHEAD;
    const float* kbase = g_k + ((b * NH + h) * SEQ) * DHEAD;
    const float* vbase = g_v + ((b * NH + h) * SEQ) * DHEAD;

    int t = threadIdx.x;
    int ty = t >> 4, tx = t & 15;

    #pragma unroll
    for (int i = 0; i < 16; i++) {
        int e = t + i * 256;
        int row = e >> 6, col = e & 63;
        Qs[row * 65 + col] = qbase[(q0 + row) * DHEAD + col];
    }

    float zacc[4][4] = {};

    for (int kt = 0; kt <= qt; kt++) {
        int k0 = kt * 64;
        __syncthreads();               // protect Ks/Vs/Ss reuse
        #pragma unroll
        for (int i = 0; i < 16; i++) {
            int e = t + i * 256;
            int row = e >> 6, col = e & 63;
            Ks[row * 65 + col] = kbase[(k0 + row) * DHEAD + col];
            Vs[row * 64 + col] = vbase[(k0 + row) * DHEAD + col];
        }
        __syncthreads();

        float acc[4][4] = {};
        #pragma unroll
        for (int d = 0; d < 64; d++) {
            float a[4], bb[4];
            #pragma unroll
            for (int i = 0; i < 4; i++) a[i]  = Qs[(ty * 4 + i) * 65 + d];
            #pragma unroll
            for (int j = 0; j < 4; j++) bb[j] = Ks[(tx * 4 + j) * 65 + d];
            #pragma unroll
            for (int i = 0; i < 4; i++)
                #pragma unroll
                for (int j = 0; j < 4; j++)
                    acc[i][j] += a[i] * bb[j];
        }

        bool edge = (kt == qt);
        #pragma unroll
        for (int i = 0; i < 4; i++) {
            int qi = q0 + ty * 4 + i;
            #pragma unroll
            for (int j = 0; j < 4; j++) {
                int kj = k0 + tx * 4 + j;
                float sv = acc[i][j] * (1.0f / 64.0f);
                sv = sv * sv;
                if (edge && kj > qi) sv = 0.0f;
                Ss[(ty * 4 + i) * 68 + tx * 4 + j] = sv;
            }
        }
        __syncthreads();

        #pragma unroll
        for (int jj = 0; jj < 64; jj++) {
            float a[4], bv[4];
            #pragma unroll
            for (int i = 0; i < 4; i++) a[i]  = Ss[(ty * 4 + i) * 68 + jj];
            #pragma unroll
            for (int l = 0; l < 4; l++) bv[l] = Vs[jj * 64 + tx * 4 + l];
            #pragma unroll
            for (int i = 0; i < 4; i++)
                #pragma unroll
                for (int l = 0; l < 4; l++)
                    zacc[i][l] += a[i] * bv[l];
        }
    }

    float* zbase = g_z + ((b * NH + h) * SEQ) * DHEAD;
    #pragma unroll
    for (int i = 0; i < 4; i++)
        #pragma unroll
        for (int l = 0; l < 4; l++)
            zbase[(q0 + ty * 4 + i) * DHEAD + tx * 4 + l] = zacc[i][l];
}

// ---------------------------------------------------------------------------
// Kernel 4: out = x + Z @ Wo^T.  Z read from [b][h][s][d] scratch layout.
// ---------------------------------------------------------------------------
__global__ void out_gemm(const float* __restrict__ x,
                         const float* __restrict__ Wo,
                         float* __restrict__ out)
{
    __shared__ float As[16][65];
    __shared__ float Bs[16][65];

    int n0 = blockIdx.x * 64;
    int m0 = blockIdx.y * 64;
    int t  = threadIdx.x;
    int ty = t >> 4, tx = t & 15;
    int lr = t >> 4, lc = t & 15;

    float acc[4][4] = {};

    for (int k0 = 0; k0 < DMODEL; k0 += 16) {
        #pragma unroll
        for (int r = 0; r < 4; r++) {
            int row = lr + r * 16;
            int m = m0 + row;
            int k = k0 + lc;
            int b = m >> 11, s = m & (SEQ - 1);
            int hh = k >> 6, d = k & 63;
            As[lc][row] = g_z[(((b * NH + hh) * SEQ) + s) * DHEAD + d];
            Bs[lc][row] = Wo[(n0 + row) * DMODEL + k];
        }
        __syncthreads();
        #pragma unroll
        for (int kk = 0; kk < 16; kk++) {
            float a[4], b[4];
            #pragma unroll
            for (int i = 0; i < 4; i++) a[i] = As[kk][ty * 4 + i];
            #pragma unroll
            for (int j = 0; j < 4; j++) b[j] = Bs[kk][tx * 4 + j];
            #pragma unroll
            for (int i = 0; i < 4; i++)
                #pragma unroll
                for (int j = 0; j < 4; j++)
                    acc[i][j] += a[i] * b[j];
        }
        __syncthreads();
    }

    #pragma unroll
    for (int i = 0; i < 4; i++) {
        int m = m0 + ty * 4 + i;
        #pragma unroll
        for (int j = 0; j < 4; j++) {
            int n = n0 + tx * 4 + j;
            out[m * DMODEL + n] = x[m * DMODEL + n] + acc[i][j];
        }
    }
}

// ---------------------------------------------------------------------------
extern "C" void kernel_launch(void* const* d_in, const int* in_sizes, int n_in,
                              void* d_out, int out_size)
{
    const float* x  = (const float*)d_in[0];
    const float* Wq = (const float*)d_in[1];
    const float* bq = (const float*)d_in[2];
    const float* Wk = (const float*)d_in[3];
    const float* bk = (const float*)d_in[4];
    const float* Wv = (const float*)d_in[5];
    const float* bv = (const float*)d_in[6];
    const float* Wo = (const float*)d_in[7];
    const float* nw = (const float*)d_in[8];
    float* out = (float*)d_out;

    qkv_gemm<<<dim3(48, 64), 256>>>(x, Wq, bq, Wk, bk, Wv, bv);
    normrope<<<16384, 256>>>(nw);

    size_t smem = (size_t)(64 * 65 * 2 + 64 * 68 + 64 * 64) * sizeof(float);
    cudaFuncSetAttribute(attn_kernel, cudaFuncAttributeMaxDynamicSharedMemorySize,
                         (int)smem);
    attn_kernel<<<dim3(SEQ / 64, NH, NB), 256, smem>>>();

    out_gemm<<<dim3(16, 64), 256>>>(x, Wo, out);
}

// round 2
// speedup vs baseline: 2.1638x; 2.1638x over previous
#include <cuda_runtime.h>

#define NB     2
#define NH     16
#define SEQ    2048
#define DMODEL 1024
#define DHEAD  64

__device__ float g_q[NB*NH*SEQ*DHEAD];
__device__ float g_k[NB*NH*SEQ*DHEAD];
__device__ float g_v[NB*NH*SEQ*DHEAD];
__device__ float g_z[NB*NH*SEQ*DHEAD];

// ---------------------------------------------------------------------------
// QKV projection: C = x @ W^T + b, scattered to [b][h][s][d].
// 128x128x16 tiles, 256 threads, 8x8/thread, k-major smem, float4 LDS.
// ---------------------------------------------------------------------------
__global__ __launch_bounds__(256) void qkv_gemm(
    const float* __restrict__ x,
    const float* __restrict__ Wq, const float* __restrict__ bq,
    const float* __restrict__ Wk, const float* __restrict__ bk,
    const float* __restrict__ Wv, const float* __restrict__ bv)
{
    __shared__ float As[16][132];
    __shared__ float Bs[16][132];

    int bx = blockIdx.x;              // 0..23
    int by = blockIdx.y;              // 0..31
    int which = bx >> 3;
    const float* W    = (which == 0) ? Wq : (which == 1) ? Wk : Wv;
    const float* bias = (which == 0) ? bq : (which == 1) ? bk : bv;
    float* outbuf     = (which == 0) ? g_q : (which == 1) ? g_k : g_v;
    int n0 = (bx & 7) * 128;
    int m0 = by * 128;

    int t  = threadIdx.x;
    int ty = t >> 4, tx = t & 15;

    // loader mapping: 2 float4 per thread per operand per chunk
    int f4a = t * 2, f4b = t * 2 + 1;
    int rA0 = f4a >> 2, cA0 = (f4a & 3) * 4;
    int rA1 = f4b >> 2, cA1 = (f4b & 3) * 4;

    float acc[8][8] = {};
    float4 pa0, pa1, pb0, pb1;

    // prefetch chunk 0
    pa0 = *(const float4*)&x[(m0 + rA0) * DMODEL + 0 + cA0];
    pa1 = *(const float4*)&x[(m0 + rA1) * DMODEL + 0 + cA1];
    pb0 = *(const float4*)&W[(n0 + rA0) * DMODEL + 0 + cA0];
    pb1 = *(const float4*)&W[(n0 + rA1) * DMODEL + 0 + cA1];

    for (int k0 = 0; k0 < DMODEL; k0 += 16) {
        // store current chunk (transposed to k-major)
        As[cA0+0][rA0] = pa0.x; As[cA0+1][rA0] = pa0.y; As[cA0+2][rA0] = pa0.z; As[cA0+3][rA0] = pa0.w;
        As[cA1+0][rA1] = pa1.x; As[cA1+1][rA1] = pa1.y; As[cA1+2][rA1] = pa1.z; As[cA1+3][rA1] = pa1.w;
        Bs[cA0+0][rA0] = pb0.x; Bs[cA0+1][rA0] = pb0.y; Bs[cA0+2][rA0] = pb0.z; Bs[cA0+3][rA0] = pb0.w;
        Bs[cA1+0][rA1] = pb1.x; Bs[cA1+1][rA1] = pb1.y; Bs[cA1+2][rA1] = pb1.z; Bs[cA1+3][rA1] = pb1.w;
        __syncthreads();

        int kn = k0 + 16;
        if (kn < DMODEL) {
            pa0 = *(const float4*)&x[(m0 + rA0) * DMODEL + kn + cA0];
            pa1 = *(const float4*)&x[(m0 + rA1) * DMODEL + kn + cA1];
            pb0 = *(const float4*)&W[(n0 + rA0) * DMODEL + kn + cA0];
            pb1 = *(const float4*)&W[(n0 + rA1) * DMODEL + kn + cA1];
        }

        #pragma unroll
        for (int kk = 0; kk < 16; kk++) {
            float4 a0 = *(float4*)&As[kk][ty * 8];
            float4 a1 = *(float4*)&As[kk][ty * 8 + 4];
            float4 b0 = *(float4*)&Bs[kk][tx * 8];
            float4 b1 = *(float4*)&Bs[kk][tx * 8 + 4];
            float av[8] = {a0.x,a0.y,a0.z,a0.w,a1.x,a1.y,a1.z,a1.w};
            float bv[8] = {b0.x,b0.y,b0.z,b0.w,b1.x,b1.y,b1.z,b1.w};
            #pragma unroll
            for (int i = 0; i < 8; i++)
                #pragma unroll
                for (int j = 0; j < 8; j++)
                    acc[i][j] += av[i] * bv[j];
        }
        __syncthreads();
    }

    #pragma unroll
    for (int i = 0; i < 8; i++) {
        int m = m0 + ty * 8 + i;
        int b = m >> 11, s = m & (SEQ - 1);
        #pragma unroll
        for (int j = 0; j < 8; j++) {
            int n = n0 + tx * 8 + j;
            int h = n >> 6;
            outbuf[(((b * NH + h) * SEQ) + s) * DHEAD + (n & 63)] = acc[i][j] + bias[n];
        }
    }
}

// ---------------------------------------------------------------------------
// RMSNorm + RoPE on q and k (in place). One warp per row of 64.
// ---------------------------------------------------------------------------
__global__ void normrope(const float* __restrict__ nw)
{
    int gw   = (blockIdx.x * blockDim.x + threadIdx.x) >> 5;
    int lane = threadIdx.x & 31;
    int sel  = gw >> 16;
    int idx  = gw & 65535;
    float* buf = sel ? g_k : g_q;
    int s = idx & (SEQ - 1);

    float2* p = reinterpret_cast<float2*>(buf + (size_t)idx * DHEAD) + lane;
    float2 v = *p;

    float ss = v.x * v.x + v.y * v.y;
    #pragma unroll
    for (int off = 16; off > 0; off >>= 1)
        ss += __shfl_xor_sync(0xffffffffu, ss, off);
    float scale = rsqrtf(ss * (1.0f / 64.0f) + 1.1920929e-7f);

    int d0 = lane * 2, d1 = d0 + 1;
    float xn = v.x * scale * nw[d0];
    float yn = v.y * scale * nw[d1];

    int j0 = d0 & 31, j1 = d1 & 31;
    const float c = 9.210340371976184f / 32.0f;
    float ang0 = (float)s * expf(-(float)j0 * c);
    float ang1 = (float)s * expf(-(float)j1 * c);
    float c0 = cosf(ang0), s0 = sinf(ang0);
    float c1 = cosf(ang1), s1 = sinf(ang1);

    float2 o;
    o.x = xn * c0 - yn * s0;
    o.y = yn * c1 + xn * s1;
    *p = o;
}

// ---------------------------------------------------------------------------
// Attention: per (b,h, 128-row q-tile) stream causal 128-row k-tiles.
// S = (Q.K^T/64)^2 masked; Z += S.V.  Q/K d-major smem, S m-major.
// ---------------------------------------------------------------------------
__global__ __launch_bounds__(256) void attn_kernel()
{
    extern __shared__ float sm[];
    float* Qs = sm;                    // [64][132] d-major
    float* Ks = Qs + 64 * 132;         // [64][132] d-major
    float* Vs = Ks + 64 * 132;         // [128][68] row-major
    float* Ss = Vs + 128 * 68;         // [128][132] m-major

    int qt = (int)gridDim.x - 1 - (int)blockIdx.x;   // heavy tiles first
    int h = blockIdx.y, b = blockIdx.z;
    int q0 = qt * 128;
    const float* qbase = g_q + ((size_t)(b * NH + h) * SEQ) * DHEAD;
    const float* kbase = g_k + ((size_t)(b * NH + h) * SEQ) * DHEAD;
    const float* vbase = g_v + ((size_t)(b * NH + h) * SEQ) * DHEAD;

    int t = threadIdx.x;
    int ty = t >> 4, tx = t & 15;

    // load Q, transpose to d-major
    #pragma unroll
    for (int i = 0; i < 8; i++) {
        int f4 = t + i * 256;
        int row = f4 >> 4, c4 = (f4 & 15) * 4;
        float4 v = *(const float4*)&qbase[(q0 + row) * DHEAD + c4];
        Qs[(c4+0)*132 + row] = v.x;
        Qs[(c4+1)*132 + row] = v.y;
        Qs[(c4+2)*132 + row] = v.z;
        Qs[(c4+3)*132 + row] = v.w;
    }

    float zacc[8][4] = {};

    for (int kt = 0; kt <= qt; kt++) {
        int k0 = kt * 128;
        __syncthreads();   // prev gemm2 done with Vs/Ss; Q-load done (iter 0)

        #pragma unroll
        for (int i = 0; i < 8; i++) {
            int f4 = t + i * 256;
            int row = f4 >> 4, c4 = (f4 & 15) * 4;
            float4 kv = *(const float4*)&kbase[(k0 + row) * DHEAD + c4];
            Ks[(c4+0)*132 + row] = kv.x;
            Ks[(c4+1)*132 + row] = kv.y;
            Ks[(c4+2)*132 + row] = kv.z;
            Ks[(c4+3)*132 + row] = kv.w;
            float4 vv = *(const float4*)&vbase[(k0 + row) * DHEAD + c4];
            *(float4*)&Vs[row * 68 + c4] = vv;
        }
        __syncthreads();

        // gemm1: S = Q.K^T over d=64
        float acc[8][8] = {};
        #pragma unroll
        for (int d = 0; d < 64; d++) {
            float4 a0 = *(float4*)&Qs[d * 132 + ty * 8];
            float4 a1 = *(float4*)&Qs[d * 132 + ty * 8 + 4];
            float4 b0 = *(float4*)&Ks[d * 132 + tx * 8];
            float4 b1 = *(float4*)&Ks[d * 132 + tx * 8 + 4];
            float av[8] = {a0.x,a0.y,a0.z,a0.w,a1.x,a1.y,a1.z,a1.w};
            float bv[8] = {b0.x,b0.y,b0.z,b0.w,b1.x,b1.y,b1.z,b1.w};
            #pragma unroll
            for (int i = 0; i < 8; i++)
                #pragma unroll
                for (int j = 0; j < 8; j++)
                    acc[i][j] += av[i] * bv[j];
        }

        bool edge = (kt == qt);
        #pragma unroll
        for (int i = 0; i < 8; i++) {
            int qi = q0 + ty * 8 + i;
            #pragma unroll
            for (int j4 = 0; j4 < 2; j4++) {
                float4 sv4;
                float* sp = &sv4.x;
                #pragma unroll
                for (int c = 0; c < 4; c++) {
                    int j = j4 * 4 + c;
                    int kj = k0 + tx * 8 + j;
                    float sv = acc[i][j] * (1.0f / 64.0f);
                    sv = sv * sv;
                    if (edge && kj > qi) sv = 0.0f;
                    sp[c] = sv;
                }
                *(float4*)&Ss[(ty * 8 + i) * 132 + tx * 8 + j4 * 4] = sv4;
            }
        }
        __syncthreads();

        // gemm2: Z += S.V over j=128, thread tile 8 rows x 4 dcols
        #pragma unroll 8
        for (int j4 = 0; j4 < 128; j4 += 4) {
            float4 av4[8];
            #pragma unroll
            for (int i = 0; i < 8; i++)
                av4[i] = *(float4*)&Ss[(ty * 8 + i) * 132 + j4];
            float4 bv4[4];
            #pragma unroll
            for (int jj = 0; jj < 4; jj++)
                bv4[jj] = *(float4*)&Vs[(j4 + jj) * 68 + tx * 4];
            #pragma unroll
            for (int jj = 0; jj < 4; jj++) {
                float aj;
                #pragma unroll
                for (int i = 0; i < 8; i++) {
                    aj = (jj == 0) ? av4[i].x : (jj == 1) ? av4[i].y : (jj == 2) ? av4[i].z : av4[i].w;
                    zacc[i][0] += aj * bv4[jj].x;
                    zacc[i][1] += aj * bv4[jj].y;
                    zacc[i][2] += aj * bv4[jj].z;
                    zacc[i][3] += aj * bv4[jj].w;
                }
            }
        }
    }

    float* zbase = g_z + ((size_t)(b * NH + h) * SEQ) * DHEAD;
    #pragma unroll
    for (int i = 0; i < 8; i++) {
        float4 o = make_float4(zacc[i][0], zacc[i][1], zacc[i][2], zacc[i][3]);
        *(float4*)&zbase[(q0 + ty * 8 + i) * DHEAD + tx * 4] = o;
    }
}

// ---------------------------------------------------------------------------
// out = x + Z @ Wo^T. Z gathered from [b][h][s][d].
// ---------------------------------------------------------------------------
__global__ __launch_bounds__(256) void out_gemm(
    const float* __restrict__ x,
    const float* __restrict__ Wo,
    float* __restrict__ out)
{
    __shared__ float As[16][132];
    __shared__ float Bs[16][132];

    int n0 = blockIdx.x * 128;
    int m0 = blockIdx.y * 128;
    int t  = threadIdx.x;
    int ty = t >> 4, tx = t & 15;

    int f4a = t * 2, f4b = t * 2 + 1;
    int rA0 = f4a >> 2, cA0 = (f4a & 3) * 4;
    int rA1 = f4b >> 2, cA1 = (f4b & 3) * 4;

    // Z gather address helper (4 consecutive k stay in one head)
    int mA0 = m0 + rA0, mA1 = m0 + rA1;
    int bA0 = mA0 >> 11, sA0 = mA0 & (SEQ - 1);
    int bA1 = mA1 >> 11, sA1 = mA1 & (SEQ - 1);

    float acc[8][8] = {};
    float4 pa0, pa1, pb0, pb1;

    {
        int k0 = 0;
        int kA0 = k0 + cA0, kA1 = k0 + cA1;
        pa0 = *(const float4*)&g_z[(((bA0 * NH + (kA0 >> 6)) * SEQ) + sA0) * DHEAD + (kA0 & 63)];
        pa1 = *(const float4*)&g_z[(((bA1 * NH + (kA1 >> 6)) * SEQ) + sA1) * DHEAD + (kA1 & 63)];
        pb0 = *(const float4*)&Wo[(n0 + rA0) * DMODEL + kA0];
        pb1 = *(const float4*)&Wo[(n0 + rA1) * DMODEL + kA1];
    }

    for (int k0 = 0; k0 < DMODEL; k0 += 16) {
        As[cA0+0][rA0] = pa0.x; As[cA0+1][rA0] = pa0.y; As[cA0+2][rA0] = pa0.z; As[cA0+3][rA0] = pa0.w;
        As[cA1+0][rA1] = pa1.x; As[cA1+1][rA1] = pa1.y; As[cA1+2][rA1] = pa1.z; As[cA1+3][rA1] = pa1.w;
        Bs[cA0+0][rA0] = pb0.x; Bs[cA0+1][rA0] = pb0.y; Bs[cA0+2][rA0] = pb0.z; Bs[cA0+3][rA0] = pb0.w;
        Bs[cA1+0][rA1] = pb1.x; Bs[cA1+1][rA1] = pb1.y; Bs[cA1+2][rA1] = pb1.z; Bs[cA1+3][rA1] = pb1.w;
        __syncthreads();

        int kn = k0 + 16;
        if (kn < DMODEL) {
            int kA0 = kn + cA0, kA1 = kn + cA1;
            pa0 = *(const float4*)&g_z[(((bA0 * NH + (kA0 >> 6)) * SEQ) + sA0) * DHEAD + (kA0 & 63)];
            pa1 = *(const float4*)&g_z[(((bA1 * NH + (kA1 >> 6)) * SEQ) + sA1) * DHEAD + (kA1 & 63)];
            pb0 = *(const float4*)&Wo[(n0 + rA0) * DMODEL + kA0];
            pb1 = *(const float4*)&Wo[(n0 + rA1) * DMODEL + kA1];
        }

        #pragma unroll
        for (int kk = 0; kk < 16; kk++) {
            float4 a0 = *(float4*)&As[kk][ty * 8];
            float4 a1 = *(float4*)&As[kk][ty * 8 + 4];
            float4 b0 = *(float4*)&Bs[kk][tx * 8];
            float4 b1 = *(float4*)&Bs[kk][tx * 8 + 4];
            float av[8] = {a0.x,a0.y,a0.z,a0.w,a1.x,a1.y,a1.z,a1.w};
            float bv[8] = {b0.x,b0.y,b0.z,b0.w,b1.x,b1.y,b1.z,b1.w};
            #pragma unroll
            for (int i = 0; i < 8; i++)
                #pragma unroll
                for (int j = 0; j < 8; j++)
                    acc[i][j] += av[i] * bv[j];
        }
        __syncthreads();
    }

    #pragma unroll
    for (int i = 0; i < 8; i++) {
        int m = m0 + ty * 8 + i;
        #pragma unroll
        for (int j4 = 0; j4 < 2; j4++) {
            int n = n0 + tx * 8 + j4 * 4;
            float4 xr = *(const float4*)&x[m * DMODEL + n];
            float4 o = make_float4(xr.x + acc[i][j4*4+0], xr.y + acc[i][j4*4+1],
                                   xr.z + acc[i][j4*4+2], xr.w + acc[i][j4*4+3]);
            *(float4*)&out[m * DMODEL + n] = o;
        }
    }
}

// ---------------------------------------------------------------------------
extern "C" void kernel_launch(void* const* d_in, const int* in_sizes, int n_in,
                              void* d_out, int out_size)
{
    const float* x  = (const float*)d_in[0];
    const float* Wq = (const float*)d_in[1];
    const float* bq = (const float*)d_in[2];
    const float* Wk = (const float*)d_in[3];
    const float* bk = (const float*)d_in[4];
    const float* Wv = (const float*)d_in[5];
    const float* bv = (const float*)d_in[6];
    const float* Wo = (const float*)d_in[7];
    const float* nw = (const float*)d_in[8];
    float* out = (float*)d_out;

    qkv_gemm<<<dim3(24, 32), 256>>>(x, Wq, bq, Wk, bk, Wv, bv);
    normrope<<<16384, 256>>>(nw);

    size_t smem = (size_t)(64*132*2 + 128*68 + 128*132) * sizeof(float);
    static int smem_set = 0;
    if (!smem_set) {
        cudaFuncSetAttribute(attn_kernel, cudaFuncAttributeMaxDynamicSharedMemorySize,
                             (int)smem);
        smem_set = 1;
    }
    attn_kernel<<<dim3(SEQ / 128, NH, NB), 256, smem>>>();

    out_gemm<<<dim3(8, 32), 256>>>(x, Wo, out);
}